// round 12
// baseline (speedup 1.0000x reference)
#include <cuda_runtime.h>

// DyDepthwiseConvAtten, R11: TWO-PASS split to shorten per-row dependency
// chains (the fused kernel converged to a 5.65 TB/s sustained-BW wall at
// 55.8us across three different bodies).
//   Pass 1: w[row] = q[row] . Ww^T + bw  (reads q 105MB, writes 1.6MB scratch)
//           -> pure streaming reduction, near-peak read BW.
//   Pass 2: conv3 + LayerNorm (reads v 105MB + w from L2, writes out 105MB)
//           -> weight reduction off the critical path entirely.

#define C_DIM  256
#define LN_EPS 1e-5f
#define FULL   0xFFFFFFFFu
#define MAX_ROWS 102400

__device__ float g_w[MAX_ROWS * 4];   // {w0,w1,w2,pad} per row, 1.6MB (L2-resident)

// ---------------- Pass 1: dynamic weights ----------------
__global__ __launch_bounds__(256)
void weights_kernel(const float* __restrict__ q,
                    const float* __restrict__ Ww,   // [3,256]
                    const float* __restrict__ bw,   // [3]
                    int rows, int total_warps)
{
    const int warp_g = (blockIdx.x * blockDim.x + threadIdx.x) >> 5;
    const int lane   = threadIdx.x & 31;
    const int cbase  = lane * 8;

    // hoist Ww rows into registers
    float W0[8], W1[8], W2[8];
    {
        const float4* p;
        float4 a, b;
        p = (const float4*)(Ww + 0 * C_DIM + cbase); a = p[0]; b = p[1];
        W0[0]=a.x; W0[1]=a.y; W0[2]=a.z; W0[3]=a.w; W0[4]=b.x; W0[5]=b.y; W0[6]=b.z; W0[7]=b.w;
        p = (const float4*)(Ww + 1 * C_DIM + cbase); a = p[0]; b = p[1];
        W1[0]=a.x; W1[1]=a.y; W1[2]=a.z; W1[3]=a.w; W1[4]=b.x; W1[5]=b.y; W1[6]=b.z; W1[7]=b.w;
        p = (const float4*)(Ww + 2 * C_DIM + cbase); a = p[0]; b = p[1];
        W2[0]=a.x; W2[1]=a.y; W2[2]=a.z; W2[3]=a.w; W2[4]=b.x; W2[5]=b.y; W2[6]=b.z; W2[7]=b.w;
    }
    const float bw0 = bw[0], bw1 = bw[1], bw2 = bw[2];

    for (int row = warp_g; row < rows; row += total_warps) {
        const size_t base = (size_t)row * C_DIM + cbase;
        const float4 qa = ((const float4*)(q + base))[0];
        const float4 qb = ((const float4*)(q + base))[1];
        float Q[8] = {qa.x, qa.y, qa.z, qa.w, qb.x, qb.y, qb.z, qb.w};

        float p0 = 0.f, p1 = 0.f, p2 = 0.f;
        #pragma unroll
        for (int i = 0; i < 8; i++) {
            p0 = fmaf(Q[i], W0[i], p0);
            p1 = fmaf(Q[i], W1[i], p1);
            p2 = fmaf(Q[i], W2[i], p2);
        }
        #pragma unroll
        for (int off = 16; off > 0; off >>= 1) {
            p0 += __shfl_xor_sync(FULL, p0, off);
            p1 += __shfl_xor_sync(FULL, p1, off);
            p2 += __shfl_xor_sync(FULL, p2, off);
        }
        if (lane == 0) {
            float4 wv;
            wv.x = bw0 + p0;
            wv.y = bw1 + p1;
            wv.z = bw2 + p2;
            wv.w = 0.f;
            ((float4*)g_w)[row] = wv;
        }
    }
}

// ---------------- Pass 2: conv3 + LayerNorm ----------------
__global__ __launch_bounds__(256)
void conv_ln_kernel(const float* __restrict__ v,
                    const float* __restrict__ gamma,
                    const float* __restrict__ beta,
                    float* __restrict__ out,
                    int rows, int total_warps)
{
    const int warp_g = (blockIdx.x * blockDim.x + threadIdx.x) >> 5;
    const int lane   = threadIdx.x & 31;
    const int cbase  = lane * 8;

    float G[8], Bt[8];
    {
        const float4* p;
        float4 a, b;
        p = (const float4*)(gamma + cbase); a = p[0]; b = p[1];
        G[0]=a.x; G[1]=a.y; G[2]=a.z; G[3]=a.w; G[4]=b.x; G[5]=b.y; G[6]=b.z; G[7]=b.w;
        p = (const float4*)(beta + cbase); a = p[0]; b = p[1];
        Bt[0]=a.x; Bt[1]=a.y; Bt[2]=a.z; Bt[3]=a.w; Bt[4]=b.x; Bt[5]=b.y; Bt[6]=b.z; Bt[7]=b.w;
    }

    for (int row = warp_g; row < rows; row += total_warps) {
        const size_t base = (size_t)row * C_DIM + cbase;

        const float4 va = ((const float4*)(v + base))[0];
        const float4 vb = ((const float4*)(v + base))[1];
        // broadcast load of this row's weights (1.6MB buffer: L2-resident)
        const float4 wv = __ldg((const float4*)g_w + row);
        float V[8] = {va.x, va.y, va.z, va.w, vb.x, vb.y, vb.z, vb.w};
        const float w0 = wv.x, w1 = wv.y, w2 = wv.z;

        // halo exchange (zero padded)
        float vl = __shfl_up_sync(FULL, V[7], 1);
        float vr = __shfl_down_sync(FULL, V[0], 1);
        if (lane == 0)  vl = 0.f;
        if (lane == 31) vr = 0.f;

        // 3-tap conv + LN partials
        float O[8];
        O[0] = vl * w0 + V[0] * w1 + V[1] * w2;
        #pragma unroll
        for (int i = 1; i < 7; i++)
            O[i] = V[i - 1] * w0 + V[i] * w1 + V[i + 1] * w2;
        O[7] = V[6] * w0 + V[7] * w1 + vr * w2;

        float s = 0.f, ss = 0.f;
        #pragma unroll
        for (int i = 0; i < 8; i++) {
            s += O[i];
            ss = fmaf(O[i], O[i], ss);
        }
        #pragma unroll
        for (int off = 16; off > 0; off >>= 1) {
            s  += __shfl_xor_sync(FULL, s,  off);
            ss += __shfl_xor_sync(FULL, ss, off);
        }
        const float mean = s  * (1.0f / C_DIM);
        const float var  = ss * (1.0f / C_DIM) - mean * mean;
        const float inv  = rsqrtf(var + LN_EPS);

        float4 o0, o1;
        o0.x = (O[0] - mean) * inv * G[0] + Bt[0];
        o0.y = (O[1] - mean) * inv * G[1] + Bt[1];
        o0.z = (O[2] - mean) * inv * G[2] + Bt[2];
        o0.w = (O[3] - mean) * inv * G[3] + Bt[3];
        o1.x = (O[4] - mean) * inv * G[4] + Bt[4];
        o1.y = (O[5] - mean) * inv * G[5] + Bt[5];
        o1.z = (O[6] - mean) * inv * G[6] + Bt[6];
        o1.w = (O[7] - mean) * inv * G[7] + Bt[7];
        ((float4*)(out + base))[0] = o0;
        ((float4*)(out + base))[1] = o1;
    }
}

extern "C" void kernel_launch(void* const* d_in, const int* in_sizes, int n_in,
                              void* d_out, int out_size)
{
    const float* q     = (const float*)d_in[0];
    const float* v     = (const float*)d_in[1];
    const float* Ww    = (const float*)d_in[2];
    const float* bw    = (const float*)d_in[3];
    const float* gamma = (const float*)d_in[4];
    const float* beta  = (const float*)d_in[5];
    float* out = (float*)d_out;

    const int rows = in_sizes[0] / C_DIM;        // 102400
    const int grid = 1184;                       // 148 SMs * 8 CTAs
    const int total_warps = grid * (256 / 32);   // 9472

    weights_kernel<<<grid, 256>>>(q, Ww, bw, rows, total_warps);
    conv_ln_kernel<<<grid, 256>>>(v, gamma, beta, out, rows, total_warps);
}

// round 13
// speedup vs baseline: 1.5086x; 1.5086x over previous
#include <cuda_runtime.h>

// DyDepthwiseConvAtten fused: dynamic 3-tap depthwise conv along C + LayerNorm.
// B*N = 102400 rows, C = 256. R12 = R10 body with PACKED lane->channel map:
// lane L owns channels [4L,4L+4) and [128+4L,128+4L+4), so every LDG.128 /
// STG.128 is a contiguous 512B warp span (4 cache lines) instead of a 1KB
// span (8 lines). Halves L1tex wavefronts per row; DRAM traffic unchanged.
// Halo needs 6 shuffles (extra chunk boundary at c=127/128).

#define C_DIM  256
#define LN_EPS 1e-5f
#define FULL   0xFFFFFFFFu

__global__ __launch_bounds__(256)
void dydwconv_ln_kernel(const float* __restrict__ q,
                        const float* __restrict__ v,
                        const float* __restrict__ Ww,     // [3,256]
                        const float* __restrict__ bw,     // [3]
                        const float* __restrict__ gamma,  // [256]
                        const float* __restrict__ beta,   // [256]
                        float* __restrict__ out,
                        int rows, int total_warps)
{
    const int warp_g = (blockIdx.x * blockDim.x + threadIdx.x) >> 5;
    const int lane   = threadIdx.x & 31;
    const int cA     = lane * 4;           // chunk A: channels [cA, cA+4)
    const int cB     = 128 + lane * 4;     // chunk B: channels [cB, cB+4)

    // ---- hoisted constants (registers), packed layout ----
    float W0[8], W1[8], W2[8], G[8], Bt[8];   // [0..3]=chunk A, [4..7]=chunk B
    {
        float4 a, b;
        a = *(const float4*)(Ww + 0 * C_DIM + cA);  b = *(const float4*)(Ww + 0 * C_DIM + cB);
        W0[0]=a.x; W0[1]=a.y; W0[2]=a.z; W0[3]=a.w; W0[4]=b.x; W0[5]=b.y; W0[6]=b.z; W0[7]=b.w;
        a = *(const float4*)(Ww + 1 * C_DIM + cA);  b = *(const float4*)(Ww + 1 * C_DIM + cB);
        W1[0]=a.x; W1[1]=a.y; W1[2]=a.z; W1[3]=a.w; W1[4]=b.x; W1[5]=b.y; W1[6]=b.z; W1[7]=b.w;
        a = *(const float4*)(Ww + 2 * C_DIM + cA);  b = *(const float4*)(Ww + 2 * C_DIM + cB);
        W2[0]=a.x; W2[1]=a.y; W2[2]=a.z; W2[3]=a.w; W2[4]=b.x; W2[5]=b.y; W2[6]=b.z; W2[7]=b.w;
        a = *(const float4*)(gamma + cA);           b = *(const float4*)(gamma + cB);
        G[0]=a.x; G[1]=a.y; G[2]=a.z; G[3]=a.w; G[4]=b.x; G[5]=b.y; G[6]=b.z; G[7]=b.w;
        a = *(const float4*)(beta + cA);            b = *(const float4*)(beta + cB);
        Bt[0]=a.x; Bt[1]=a.y; Bt[2]=a.z; Bt[3]=a.w; Bt[4]=b.x; Bt[5]=b.y; Bt[6]=b.z; Bt[7]=b.w;
    }
    const float bw0 = bw[0], bw1 = bw[1], bw2 = bw[2];

    for (int row = warp_g; row < rows; row += total_warps) {
        const size_t rbase = (size_t)row * C_DIM;

        // ---- 4 contiguous-span LDG.128 (each = 512B warp span, 4 lines) ----
        const float4 qa = *(const float4*)(q + rbase + cA);
        const float4 qb = *(const float4*)(q + rbase + cB);
        const float4 va = *(const float4*)(v + rbase + cA);
        const float4 vb = *(const float4*)(v + rbase + cB);

        float Q[8] = {qa.x, qa.y, qa.z, qa.w, qb.x, qb.y, qb.z, qb.w};
        float V[8] = {va.x, va.y, va.z, va.w, vb.x, vb.y, vb.z, vb.w};

        // ---- dynamic kernel weights: w_k = bw[k] + sum_c q[c]*Ww[k][c] ----
        float p0 = 0.f, p1 = 0.f, p2 = 0.f;
        #pragma unroll
        for (int i = 0; i < 8; i++) {
            p0 = fmaf(Q[i], W0[i], p0);
            p1 = fmaf(Q[i], W1[i], p1);
            p2 = fmaf(Q[i], W2[i], p2);
        }
        #pragma unroll
        for (int off = 16; off > 0; off >>= 1) {
            p0 += __shfl_xor_sync(FULL, p0, off);
            p1 += __shfl_xor_sync(FULL, p1, off);
            p2 += __shfl_xor_sync(FULL, p2, off);
        }
        const float w0 = bw0 + p0;
        const float w1 = bw1 + p1;
        const float w2 = bw2 + p2;

        // ---- halo exchange, packed layout (zero padded at c=0 and c=255) ----
        float vAl = __shfl_up_sync(FULL, V[3], 1);     // v[4L-1]
        float vBl = __shfl_up_sync(FULL, V[7], 1);     // v[128+4L-1]
        float vAr = __shfl_down_sync(FULL, V[0], 1);   // v[4L+4]
        float vBr = __shfl_down_sync(FULL, V[4], 1);   // v[128+4L+4]
        const float v127 = __shfl_sync(FULL, V[3], 31);
        const float v128 = __shfl_sync(FULL, V[4], 0);
        if (lane == 0)  { vAl = 0.f;  vBl = v127; }
        if (lane == 31) { vAr = v128; vBr = 0.f; }

        // ---- 3-tap conv per chunk + LN partials ----
        float O[8];
        O[0] = vAl  * w0 + V[0] * w1 + V[1] * w2;
        O[1] = V[0] * w0 + V[1] * w1 + V[2] * w2;
        O[2] = V[1] * w0 + V[2] * w1 + V[3] * w2;
        O[3] = V[2] * w0 + V[3] * w1 + vAr  * w2;
        O[4] = vBl  * w0 + V[4] * w1 + V[5] * w2;
        O[5] = V[4] * w0 + V[5] * w1 + V[6] * w2;
        O[6] = V[5] * w0 + V[6] * w1 + V[7] * w2;
        O[7] = V[6] * w0 + V[7] * w1 + vBr  * w2;

        float s = 0.f, ss = 0.f;
        #pragma unroll
        for (int i = 0; i < 8; i++) {
            s += O[i];
            ss = fmaf(O[i], O[i], ss);
        }
        #pragma unroll
        for (int off = 16; off > 0; off >>= 1) {
            s  += __shfl_xor_sync(FULL, s,  off);
            ss += __shfl_xor_sync(FULL, ss, off);
        }
        const float mean = s  * (1.0f / C_DIM);
        const float var  = ss * (1.0f / C_DIM) - mean * mean;
        const float inv  = rsqrtf(var + LN_EPS);

        // ---- normalize + affine + 2 contiguous-span STG.128 ----
        float4 oa, ob;
        oa.x = (O[0] - mean) * inv * G[0] + Bt[0];
        oa.y = (O[1] - mean) * inv * G[1] + Bt[1];
        oa.z = (O[2] - mean) * inv * G[2] + Bt[2];
        oa.w = (O[3] - mean) * inv * G[3] + Bt[3];
        ob.x = (O[4] - mean) * inv * G[4] + Bt[4];
        ob.y = (O[5] - mean) * inv * G[5] + Bt[5];
        ob.z = (O[6] - mean) * inv * G[6] + Bt[6];
        ob.w = (O[7] - mean) * inv * G[7] + Bt[7];
        *(float4*)(out + rbase + cA) = oa;
        *(float4*)(out + rbase + cB) = ob;
    }
}

extern "C" void kernel_launch(void* const* d_in, const int* in_sizes, int n_in,
                              void* d_out, int out_size)
{
    const float* q     = (const float*)d_in[0];
    const float* v     = (const float*)d_in[1];
    const float* Ww    = (const float*)d_in[2];
    const float* bw    = (const float*)d_in[3];
    const float* gamma = (const float*)d_in[4];
    const float* beta  = (const float*)d_in[5];
    float* out = (float*)d_out;

    const int rows = in_sizes[0] / C_DIM;        // 102400
    const int grid = 1184;                       // 148 SMs * 8 CTAs
    const int total_warps = grid * (256 / 32);   // 9472
    dydwconv_ln_kernel<<<grid, 256>>>(q, v, Ww, bw, gamma, beta, out,
                                      rows, total_warps);
}

// round 14
// speedup vs baseline: 1.5705x; 1.0410x over previous
#include <cuda_runtime.h>

// DyDepthwiseConvAtten fused: dynamic 3-tap depthwise conv along C + LayerNorm.
// B*N = 102400 rows, C = 256. R13 = R12 packed contiguous-span layout (lane L
// owns channels [4L,4L+4) and [128+4L,128+4L+4): every LDG.128/STG.128 is a
// contiguous 512B warp span = 4 cache lines) with gamma/beta moved OUT of
// registers into direct epilogue loads (L2-resident broadcast, off the
// reduction critical path) to trim register pressure. The kernel family is at
// the sustained-HBM roofline (315MB compulsory / ~5.65 TB/s); this is the
// minimal-overhead consolidation of the proven-best structure.

#define C_DIM  256
#define LN_EPS 1e-5f
#define FULL   0xFFFFFFFFu

__global__ __launch_bounds__(256)
void dydwconv_ln_kernel(const float* __restrict__ q,
                        const float* __restrict__ v,
                        const float* __restrict__ Ww,     // [3,256]
                        const float* __restrict__ bw,     // [3]
                        const float* __restrict__ gamma,  // [256]
                        const float* __restrict__ beta,   // [256]
                        float* __restrict__ out,
                        int rows, int total_warps)
{
    const int warp_g = (blockIdx.x * blockDim.x + threadIdx.x) >> 5;
    const int lane   = threadIdx.x & 31;
    const int cA     = lane * 4;           // chunk A: channels [cA, cA+4)
    const int cB     = 128 + lane * 4;     // chunk B: channels [cB, cB+4)

    // ---- conv-weight rows hoisted to registers (hot FMA chain only) ----
    float W0[8], W1[8], W2[8];
    {
        float4 a, b;
        a = *(const float4*)(Ww + 0 * C_DIM + cA);  b = *(const float4*)(Ww + 0 * C_DIM + cB);
        W0[0]=a.x; W0[1]=a.y; W0[2]=a.z; W0[3]=a.w; W0[4]=b.x; W0[5]=b.y; W0[6]=b.z; W0[7]=b.w;
        a = *(const float4*)(Ww + 1 * C_DIM + cA);  b = *(const float4*)(Ww + 1 * C_DIM + cB);
        W1[0]=a.x; W1[1]=a.y; W1[2]=a.z; W1[3]=a.w; W1[4]=b.x; W1[5]=b.y; W1[6]=b.z; W1[7]=b.w;
        a = *(const float4*)(Ww + 2 * C_DIM + cA);  b = *(const float4*)(Ww + 2 * C_DIM + cB);
        W2[0]=a.x; W2[1]=a.y; W2[2]=a.z; W2[3]=a.w; W2[4]=b.x; W2[5]=b.y; W2[6]=b.z; W2[7]=b.w;
    }
    const float bw0 = bw[0], bw1 = bw[1], bw2 = bw[2];

    for (int row = warp_g; row < rows; row += total_warps) {
        const size_t rbase = (size_t)row * C_DIM;

        // ---- 4 contiguous-span LDG.128 (512B warp span each) ----
        const float4 qa = *(const float4*)(q + rbase + cA);
        const float4 qb = *(const float4*)(q + rbase + cB);
        const float4 va = *(const float4*)(v + rbase + cA);
        const float4 vb = *(const float4*)(v + rbase + cB);

        float Q[8] = {qa.x, qa.y, qa.z, qa.w, qb.x, qb.y, qb.z, qb.w};
        float V[8] = {va.x, va.y, va.z, va.w, vb.x, vb.y, vb.z, vb.w};

        // ---- dynamic kernel weights: w_k = bw[k] + sum_c q[c]*Ww[k][c] ----
        float p0 = 0.f, p1 = 0.f, p2 = 0.f;
        #pragma unroll
        for (int i = 0; i < 8; i++) {
            p0 = fmaf(Q[i], W0[i], p0);
            p1 = fmaf(Q[i], W1[i], p1);
            p2 = fmaf(Q[i], W2[i], p2);
        }
        #pragma unroll
        for (int off = 16; off > 0; off >>= 1) {
            p0 += __shfl_xor_sync(FULL, p0, off);
            p1 += __shfl_xor_sync(FULL, p1, off);
            p2 += __shfl_xor_sync(FULL, p2, off);
        }
        const float w0 = bw0 + p0;
        const float w1 = bw1 + p1;
        const float w2 = bw2 + p2;

        // ---- halo exchange, packed layout (zero padded at c=0 / c=255) ----
        float vAl = __shfl_up_sync(FULL, V[3], 1);     // v[4L-1]
        float vBl = __shfl_up_sync(FULL, V[7], 1);     // v[128+4L-1]
        float vAr = __shfl_down_sync(FULL, V[0], 1);   // v[4L+4]
        float vBr = __shfl_down_sync(FULL, V[4], 1);   // v[128+4L+4]
        const float v127 = __shfl_sync(FULL, V[3], 31);
        const float v128 = __shfl_sync(FULL, V[4], 0);
        if (lane == 0)  { vAl = 0.f;  vBl = v127; }
        if (lane == 31) { vAr = v128; vBr = 0.f; }

        // ---- 3-tap conv per chunk + LN partials ----
        float O[8];
        O[0] = vAl  * w0 + V[0] * w1 + V[1] * w2;
        O[1] = V[0] * w0 + V[1] * w1 + V[2] * w2;
        O[2] = V[1] * w0 + V[2] * w1 + V[3] * w2;
        O[3] = V[2] * w0 + V[3] * w1 + vAr  * w2;
        O[4] = vBl  * w0 + V[4] * w1 + V[5] * w2;
        O[5] = V[4] * w0 + V[5] * w1 + V[6] * w2;
        O[6] = V[5] * w0 + V[6] * w1 + V[7] * w2;
        O[7] = V[6] * w0 + V[7] * w1 + vBr  * w2;

        float s = 0.f, ss = 0.f;
        #pragma unroll
        for (int i = 0; i < 8; i++) {
            s += O[i];
            ss = fmaf(O[i], O[i], ss);
        }
        #pragma unroll
        for (int off = 16; off > 0; off >>= 1) {
            s  += __shfl_xor_sync(FULL, s,  off);
            ss += __shfl_xor_sync(FULL, ss, off);
        }
        const float mean = s  * (1.0f / C_DIM);
        const float var  = ss * (1.0f / C_DIM) - mean * mean;
        const float inv  = rsqrtf(var + LN_EPS);

        // ---- gamma/beta loaded here (L2-resident 768B, off critical path) ----
        const float4 ga = __ldg((const float4*)(gamma + cA));
        const float4 gb = __ldg((const float4*)(gamma + cB));
        const float4 ba = __ldg((const float4*)(beta  + cA));
        const float4 bb = __ldg((const float4*)(beta  + cB));

        float4 oa, ob;
        oa.x = (O[0] - mean) * inv * ga.x + ba.x;
        oa.y = (O[1] - mean) * inv * ga.y + ba.y;
        oa.z = (O[2] - mean) * inv * ga.z + ba.z;
        oa.w = (O[3] - mean) * inv * ga.w + ba.w;
        ob.x = (O[4] - mean) * inv * gb.x + bb.x;
        ob.y = (O[5] - mean) * inv * gb.y + bb.y;
        ob.z = (O[6] - mean) * inv * gb.z + bb.z;
        ob.w = (O[7] - mean) * inv * gb.w + bb.w;
        *(float4*)(out + rbase + cA) = oa;
        *(float4*)(out + rbase + cB) = ob;
    }
}

extern "C" void kernel_launch(void* const* d_in, const int* in_sizes, int n_in,
                              void* d_out, int out_size)
{
    const float* q     = (const float*)d_in[0];
    const float* v     = (const float*)d_in[1];
    const float* Ww    = (const float*)d_in[2];
    const float* bw    = (const float*)d_in[3];
    const float* gamma = (const float*)d_in[4];
    const float* beta  = (const float*)d_in[5];
    float* out = (float*)d_out;

    const int rows = in_sizes[0] / C_DIM;        // 102400
    const int grid = 1184;                       // 148 SMs * 8 CTAs
    const int total_warps = grid * (256 / 32);   // 9472
    dydwconv_ln_kernel<<<grid, 256>>>(q, v, Ww, bw, gamma, beta, out,
                                      rows, total_warps);
}

// round 15
// speedup vs baseline: 1.6337x; 1.0402x over previous
#include <cuda_runtime.h>

// DyDepthwiseConvAtten fused: dynamic 3-tap depthwise conv along C + LayerNorm.
// B*N = 102400 rows, C = 256. R14 = R13 body (packed contiguous-span layout:
// lane L owns channels [4L,4L+4) and [128+4L,..+4); gamma/beta as epilogue
// loads; grid 1184) + zero-register L2 PREFETCH of the next grid-stride row's
// q/v lines at the top of each iteration. Next iteration's LDGs then land at
// L2-hit latency while the DRAM fetch overlaps this row's compute.

#define C_DIM  256
#define LN_EPS 1e-5f
#define FULL   0xFFFFFFFFu

__device__ __forceinline__ void l2_prefetch(const void* p) {
    asm volatile("prefetch.global.L2 [%0];" :: "l"(p));
}

__global__ __launch_bounds__(256)
void dydwconv_ln_kernel(const float* __restrict__ q,
                        const float* __restrict__ v,
                        const float* __restrict__ Ww,     // [3,256]
                        const float* __restrict__ bw,     // [3]
                        const float* __restrict__ gamma,  // [256]
                        const float* __restrict__ beta,   // [256]
                        float* __restrict__ out,
                        int rows, int total_warps)
{
    const int warp_g = (blockIdx.x * blockDim.x + threadIdx.x) >> 5;
    const int lane   = threadIdx.x & 31;
    const int cA     = lane * 4;           // chunk A: channels [cA, cA+4)
    const int cB     = 128 + lane * 4;     // chunk B: channels [cB, cB+4)

    // ---- conv-weight rows hoisted to registers (hot FMA chain only) ----
    float W0[8], W1[8], W2[8];
    {
        float4 a, b;
        a = *(const float4*)(Ww + 0 * C_DIM + cA);  b = *(const float4*)(Ww + 0 * C_DIM + cB);
        W0[0]=a.x; W0[1]=a.y; W0[2]=a.z; W0[3]=a.w; W0[4]=b.x; W0[5]=b.y; W0[6]=b.z; W0[7]=b.w;
        a = *(const float4*)(Ww + 1 * C_DIM + cA);  b = *(const float4*)(Ww + 1 * C_DIM + cB);
        W1[0]=a.x; W1[1]=a.y; W1[2]=a.z; W1[3]=a.w; W1[4]=b.x; W1[5]=b.y; W1[6]=b.z; W1[7]=b.w;
        a = *(const float4*)(Ww + 2 * C_DIM + cA);  b = *(const float4*)(Ww + 2 * C_DIM + cB);
        W2[0]=a.x; W2[1]=a.y; W2[2]=a.z; W2[3]=a.w; W2[4]=b.x; W2[5]=b.y; W2[6]=b.z; W2[7]=b.w;
    }
    const float bw0 = bw[0], bw1 = bw[1], bw2 = bw[2];

    for (int row = warp_g; row < rows; row += total_warps) {
        const size_t rbase = (size_t)row * C_DIM;

        // ---- L2 prefetch of next grid-stride row (clamped; 0 registers) ----
        {
            const int nrow = row + total_warps;
            const int crow = nrow < rows ? nrow : row;
            const size_t nbase = (size_t)crow * C_DIM;
            l2_prefetch(q + nbase + cA);
            l2_prefetch(q + nbase + cB);
            l2_prefetch(v + nbase + cA);
            l2_prefetch(v + nbase + cB);
        }

        // ---- 4 contiguous-span LDG.128 (512B warp span each) ----
        const float4 qa = *(const float4*)(q + rbase + cA);
        const float4 qb = *(const float4*)(q + rbase + cB);
        const float4 va = *(const float4*)(v + rbase + cA);
        const float4 vb = *(const float4*)(v + rbase + cB);

        float Q[8] = {qa.x, qa.y, qa.z, qa.w, qb.x, qb.y, qb.z, qb.w};
        float V[8] = {va.x, va.y, va.z, va.w, vb.x, vb.y, vb.z, vb.w};

        // ---- dynamic kernel weights: w_k = bw[k] + sum_c q[c]*Ww[k][c] ----
        float p0 = 0.f, p1 = 0.f, p2 = 0.f;
        #pragma unroll
        for (int i = 0; i < 8; i++) {
            p0 = fmaf(Q[i], W0[i], p0);
            p1 = fmaf(Q[i], W1[i], p1);
            p2 = fmaf(Q[i], W2[i], p2);
        }
        #pragma unroll
        for (int off = 16; off > 0; off >>= 1) {
            p0 += __shfl_xor_sync(FULL, p0, off);
            p1 += __shfl_xor_sync(FULL, p1, off);
            p2 += __shfl_xor_sync(FULL, p2, off);
        }
        const float w0 = bw0 + p0;
        const float w1 = bw1 + p1;
        const float w2 = bw2 + p2;

        // ---- halo exchange, packed layout (zero padded at c=0 / c=255) ----
        float vAl = __shfl_up_sync(FULL, V[3], 1);     // v[4L-1]
        float vBl = __shfl_up_sync(FULL, V[7], 1);     // v[128+4L-1]
        float vAr = __shfl_down_sync(FULL, V[0], 1);   // v[4L+4]
        float vBr = __shfl_down_sync(FULL, V[4], 1);   // v[128+4L+4]
        const float v127 = __shfl_sync(FULL, V[3], 31);
        const float v128 = __shfl_sync(FULL, V[4], 0);
        if (lane == 0)  { vAl = 0.f;  vBl = v127; }
        if (lane == 31) { vAr = v128; vBr = 0.f; }

        // ---- 3-tap conv per chunk + LN partials ----
        float O[8];
        O[0] = vAl  * w0 + V[0] * w1 + V[1] * w2;
        O[1] = V[0] * w0 + V[1] * w1 + V[2] * w2;
        O[2] = V[1] * w0 + V[2] * w1 + V[3] * w2;
        O[3] = V[2] * w0 + V[3] * w1 + vAr  * w2;
        O[4] = vBl  * w0 + V[4] * w1 + V[5] * w2;
        O[5] = V[4] * w0 + V[5] * w1 + V[6] * w2;
        O[6] = V[5] * w0 + V[6] * w1 + V[7] * w2;
        O[7] = V[6] * w0 + V[7] * w1 + vBr  * w2;

        float s = 0.f, ss = 0.f;
        #pragma unroll
        for (int i = 0; i < 8; i++) {
            s += O[i];
            ss = fmaf(O[i], O[i], ss);
        }
        #pragma unroll
        for (int off = 16; off > 0; off >>= 1) {
            s  += __shfl_xor_sync(FULL, s,  off);
            ss += __shfl_xor_sync(FULL, ss, off);
        }
        const float mean = s  * (1.0f / C_DIM);
        const float var  = ss * (1.0f / C_DIM) - mean * mean;
        const float inv  = rsqrtf(var + LN_EPS);

        // ---- gamma/beta loaded here (L2-resident 768B, off critical path) ----
        const float4 ga = __ldg((const float4*)(gamma + cA));
        const float4 gb = __ldg((const float4*)(gamma + cB));
        const float4 ba = __ldg((const float4*)(beta  + cA));
        const float4 bb = __ldg((const float4*)(beta  + cB));

        float4 oa, ob;
        oa.x = (O[0] - mean) * inv * ga.x + ba.x;
        oa.y = (O[1] - mean) * inv * ga.y + ba.y;
        oa.z = (O[2] - mean) * inv * ga.z + ba.z;
        oa.w = (O[3] - mean) * inv * ga.w + ba.w;
        ob.x = (O[4] - mean) * inv * gb.x + bb.x;
        ob.y = (O[5] - mean) * inv * gb.y + bb.y;
        ob.z = (O[6] - mean) * inv * gb.z + bb.z;
        ob.w = (O[7] - mean) * inv * gb.w + bb.w;
        *(float4*)(out + rbase + cA) = oa;
        *(float4*)(out + rbase + cB) = ob;
    }
}

extern "C" void kernel_launch(void* const* d_in, const int* in_sizes, int n_in,
                              void* d_out, int out_size)
{
    const float* q     = (const float*)d_in[0];
    const float* v     = (const float*)d_in[1];
    const float* Ww    = (const float*)d_in[2];
    const float* bw    = (const float*)d_in[3];
    const float* gamma = (const float*)d_in[4];
    const float* beta  = (const float*)d_in[5];
    float* out = (float*)d_out;

    const int rows = in_sizes[0] / C_DIM;        // 102400
    const int grid = 1184;                       // 148 SMs * 8 CTAs
    const int total_warps = grid * (256 / 32);   // 9472
    dydwconv_ln_kernel<<<grid, 256>>>(q, v, Ww, bw, gamma, beta, out,
                                      rows, total_warps);
}